// round 9
// baseline (speedup 1.0000x reference)
#include <cuda_runtime.h>
#include <cstdint>

// ---------------------------------------------------------------------------
// PointNet++ decoder: 3 FP modules, each = {3-NN interp + concat skip} ->
// conv1x1+BN+ReLU -> conv1x1+BN+ReLU.
// Scratch layout: X is (C_rows, B*N cols) row-major so convs are single GEMMs
// and BN stats are per-row reductions. GEMM = fp32 SIMT, 128x128x16 tile,
// 8x8 micro-tile (FFMA-issue-bound, target ~70% of fp32 peak).
// NOTE: harness target is sm_100 (no 'a') -> no tcgen05, no kind::tf32.
// ---------------------------------------------------------------------------

#define B_SZ 8
#define N0 8192
#define N1 2048
#define N2 512
#define N3 128

// scratch buffers (device globals: allocation-free scratch).
//   g_big:   X0 (192 x 65536) during FP0 concat/conv0; then reused as Y01.
__device__ float g_big[192 * (B_SZ * N0)];   // 50.3 MB
__device__ float g_Y00[128 * (B_SZ * N0)];   // 33.6 MB
__device__ float g_X2[768 * (B_SZ * N2)];    // 12.6 MB
__device__ float g_Y20[256 * (B_SZ * N2)];   // 4.2 MB
__device__ float g_F2N[256 * (B_SZ * N2)];   // 4.2 MB
__device__ float g_X1[384 * (B_SZ * N1)];    // 25.2 MB
__device__ float g_Y10[256 * (B_SZ * N1)];   // 16.8 MB (dedicated: no overrun)
__device__ float g_F1N[128 * (B_SZ * N1)];   // 8.4 MB
__device__ float g_stats[2 * 256];           // per-channel {mean, rstd}

// ---------------------------------------------------------------------------
// copy skip features (B,C,N) -> X rows [0,C), layout (C, B*N)
// ---------------------------------------------------------------------------
__global__ void copy_skip_kernel(const float* __restrict__ src,
                                 float* __restrict__ dst,
                                 int B, int C, int N) {
    size_t t = ((size_t)blockIdx.x * blockDim.x + threadIdx.x) * 4;
    int BN = B * N;
    int c = (int)(t / BN);
    int rem = (int)(t % BN);
    int b = rem / N;
    int n = rem % N;
    *(float4*)(dst + t) =
        *(const float4*)(src + ((size_t)b * C + c) * N + n);
}

// ---------------------------------------------------------------------------
// kNN(3) + inverse-distance interpolation (channel-major feats).
// feats indexed as feats[b*fb + c*fc + j]; writes X rows [c0, c0+C)
// with column index b*n + pi (row stride = B*n).
// ---------------------------------------------------------------------------
__global__ void knn_interp_kernel(const float* __restrict__ uxyz,
                                  const float* __restrict__ kxyz,
                                  const float* __restrict__ feats,
                                  float* __restrict__ X,
                                  int n, int m, int C, int c0,
                                  int fb, int fc, int B) {
    __shared__ float skx[2048];
    __shared__ float sky[2048];
    __shared__ float skz[2048];

    const int b = blockIdx.y;
    const int pi = blockIdx.x * blockDim.x + threadIdx.x;

    for (int j = threadIdx.x; j < m; j += blockDim.x) {
        const float* p = kxyz + ((size_t)b * m + j) * 3;
        skx[j] = p[0];
        sky[j] = p[1];
        skz[j] = p[2];
    }
    __syncthreads();
    if (pi >= n) return;

    const float* up = uxyz + ((size_t)b * n + pi) * 3;
    const float ux = up[0], uy = up[1], uz = up[2];

    float d0 = 1e30f, d1 = 1e30f, d2 = 1e30f;
    int i0 = 0, i1 = 0, i2 = 0;
    for (int j = 0; j < m; ++j) {
        float dx = ux - skx[j];
        float dy = uy - sky[j];
        float dz = uz - skz[j];
        float d = dx * dx + dy * dy + dz * dz;
        if (d < d2) {
            if (d < d1) {
                d2 = d1; i2 = i1;
                if (d < d0) { d1 = d0; i1 = i0; d0 = d; i0 = j; }
                else        { d1 = d;  i1 = j; }
            } else {
                d2 = d; i2 = j;
            }
        }
    }

    float r0 = 1.0f / (d0 + 1e-8f);
    float r1 = 1.0f / (d1 + 1e-8f);
    float r2 = 1.0f / (d2 + 1e-8f);
    float rs = 1.0f / (r0 + r1 + r2);
    const float w0 = r0 * rs, w1 = r1 * rs, w2 = r2 * rs;

    const float* fbase = feats + (size_t)b * fb;
    const size_t ocol = (size_t)b * n + pi;
    const size_t rowstride = (size_t)B * n;
    float* outp = X + (size_t)c0 * rowstride + ocol;
    for (int c = 0; c < C; ++c) {
        const float* fr = fbase + (size_t)c * fc;
        outp[(size_t)c * rowstride] = w0 * fr[i0] + w1 * fr[i1] + w2 * fr[i2];
    }
}

// ---------------------------------------------------------------------------
// SGEMM: C(M x N) = A(M x K) @ B(K x N), row-major fp32.
// CTA tile 128x128x16, 256 threads, 8x8 micro-tile, register-prefetch
// double buffering of the global->shared stage.
// M in {128,256}, N % 128 == 0, K % 16 == 0 (all exact for this problem).
// ---------------------------------------------------------------------------
__global__ __launch_bounds__(256) void sgemm128_kernel(
    const float* __restrict__ A, const float* __restrict__ B,
    float* __restrict__ C, int M, int N, int K) {
    __shared__ float As[16][128];  // As[k][m] (transposed on store)
    __shared__ float Bs[16][128];  // Bs[k][n]

    const int tid = threadIdx.x;
    const int bm = blockIdx.y * 128;
    const int bn = blockIdx.x * 128;
    const int tx = tid & 15;    // micro-tile col group
    const int ty = tid >> 4;    // micro-tile row group

    // A loaders: 512 float4 per tile; thread t handles idx {t, t+256}
    //   row = idx & 127, kcol = (idx >> 7) * 4
    const int a_row = tid & 127;
    const int a_c0 = (tid >> 7) * 4;        // 0 or 4
    // B loaders: idx {t, t+256}: k = idx >> 5, col = (idx & 31) * 4
    const int b_k0 = tid >> 5;              // 0..7
    const int b_col = (tid & 31) * 4;

    const float* Ap0 = A + (size_t)(bm + a_row) * K + a_c0;
    const float* Ap1 = Ap0 + 8;
    const float* Bp0 = B + (size_t)b_k0 * N + bn + b_col;
    const float* Bp1 = Bp0 + (size_t)8 * N;

    float acc[8][8];
#pragma unroll
    for (int i = 0; i < 8; ++i)
#pragma unroll
        for (int j = 0; j < 8; ++j) acc[i][j] = 0.0f;

    // prologue: fetch tile 0 into registers
    float4 pa0 = *(const float4*)(Ap0);
    float4 pa1 = *(const float4*)(Ap1);
    float4 pb0 = *(const float4*)(Bp0);
    float4 pb1 = *(const float4*)(Bp1);

    for (int k0 = 0; k0 < K; k0 += 16) {
        // store prefetched tile to shared
        As[a_c0 + 0][a_row] = pa0.x;
        As[a_c0 + 1][a_row] = pa0.y;
        As[a_c0 + 2][a_row] = pa0.z;
        As[a_c0 + 3][a_row] = pa0.w;
        As[a_c0 + 8][a_row] = pa1.x;
        As[a_c0 + 9][a_row] = pa1.y;
        As[a_c0 + 10][a_row] = pa1.z;
        As[a_c0 + 11][a_row] = pa1.w;
        *(float4*)&Bs[b_k0][b_col] = pb0;
        *(float4*)&Bs[b_k0 + 8][b_col] = pb1;
        __syncthreads();

        // prefetch next tile
        if (k0 + 16 < K) {
            pa0 = *(const float4*)(Ap0 + k0 + 16);
            pa1 = *(const float4*)(Ap1 + k0 + 16);
            pb0 = *(const float4*)(Bp0 + (size_t)(k0 + 16) * N);
            pb1 = *(const float4*)(Bp1 + (size_t)(k0 + 16) * N);
        }

#pragma unroll
        for (int kk = 0; kk < 16; ++kk) {
            float af[8], bf[8];
            *(float4*)&af[0] = *(const float4*)&As[kk][ty * 4];
            *(float4*)&af[4] = *(const float4*)&As[kk][ty * 4 + 64];
            *(float4*)&bf[0] = *(const float4*)&Bs[kk][tx * 4];
            *(float4*)&bf[4] = *(const float4*)&Bs[kk][tx * 4 + 64];
#pragma unroll
            for (int i = 0; i < 8; ++i)
#pragma unroll
                for (int j = 0; j < 8; ++j)
                    acc[i][j] = fmaf(af[i], bf[j], acc[i][j]);
        }
        __syncthreads();
    }

    // epilogue: rows bm + ty*4 + {0..3} and +64; cols bn + tx*4 (+64)
#pragma unroll
    for (int ih = 0; ih < 2; ++ih) {
#pragma unroll
        for (int i = 0; i < 4; ++i) {
            const int row = bm + ih * 64 + ty * 4 + i;
            float* cp = C + (size_t)row * N + bn;
            *(float4*)(cp + tx * 4) =
                make_float4(acc[ih * 4 + i][0], acc[ih * 4 + i][1],
                            acc[ih * 4 + i][2], acc[ih * 4 + i][3]);
            *(float4*)(cp + tx * 4 + 64) =
                make_float4(acc[ih * 4 + i][4], acc[ih * 4 + i][5],
                            acc[ih * 4 + i][6], acc[ih * 4 + i][7]);
        }
    }
}

// ---------------------------------------------------------------------------
// BN batch stats: per row (channel) of Y (C x Ncols): mean & rsqrt(var+eps)
// ---------------------------------------------------------------------------
__global__ void bn_stats_kernel(const float* __restrict__ Y,
                                float* __restrict__ stats, int Ncols) {
    const int c = blockIdx.x;
    const float* row = Y + (size_t)c * Ncols;
    float s = 0.0f, s2 = 0.0f;
    for (int i = threadIdx.x * 4; i < Ncols; i += blockDim.x * 4) {
        float4 v = *(const float4*)(row + i);
        s += v.x + v.y + v.z + v.w;
        s2 += v.x * v.x + v.y * v.y + v.z * v.z + v.w * v.w;
    }
#pragma unroll
    for (int o = 16; o; o >>= 1) {
        s += __shfl_down_sync(0xFFFFFFFFu, s, o);
        s2 += __shfl_down_sync(0xFFFFFFFFu, s2, o);
    }
    __shared__ float ws[8], ws2[8];
    const int w = threadIdx.x >> 5, l = threadIdx.x & 31;
    if (l == 0) { ws[w] = s; ws2[w] = s2; }
    __syncthreads();
    if (threadIdx.x == 0) {
        float S = 0.0f, S2 = 0.0f;
        const int nw = blockDim.x >> 5;
        for (int i = 0; i < nw; ++i) { S += ws[i]; S2 += ws2[i]; }
        const float inv = 1.0f / (float)Ncols;
        const float mean = S * inv;
        const float var = S2 * inv - mean * mean;
        stats[2 * c] = mean;
        stats[2 * c + 1] = rsqrtf(var + 1e-5f);
    }
}

// ---------------------------------------------------------------------------
// BN apply + ReLU, in place on (C x Ncols)
// ---------------------------------------------------------------------------
__global__ void bn_apply_ip_kernel(float* __restrict__ Y,
                                   const float* __restrict__ stats,
                                   const float* __restrict__ gamma,
                                   const float* __restrict__ beta,
                                   int Ncols) {
    size_t t = ((size_t)blockIdx.x * blockDim.x + threadIdx.x) * 4;
    const int c = (int)(t / Ncols);
    const float g = gamma[c] * stats[2 * c + 1];
    const float b = beta[c] - stats[2 * c] * g;
    float4 v = *(float4*)(Y + t);
    v.x = fmaxf(v.x * g + b, 0.0f);
    v.y = fmaxf(v.y * g + b, 0.0f);
    v.z = fmaxf(v.z * g + b, 0.0f);
    v.w = fmaxf(v.w * g + b, 0.0f);
    *(float4*)(Y + t) = v;
}

// ---------------------------------------------------------------------------
// BN apply + ReLU, (C, B*N) -> out (B,C,N)
// ---------------------------------------------------------------------------
__global__ void bn_apply_out_kernel(const float* __restrict__ Y,
                                    const float* __restrict__ stats,
                                    const float* __restrict__ gamma,
                                    const float* __restrict__ beta,
                                    float* __restrict__ out,
                                    int B, int C, int N) {
    size_t t = ((size_t)blockIdx.x * blockDim.x + threadIdx.x) * 4;
    const int BN = B * N;
    const int c = (int)(t / BN);
    const int rem = (int)(t % BN);
    const int b = rem / N;
    const int n = rem % N;
    const float g = gamma[c] * stats[2 * c + 1];
    const float bb = beta[c] - stats[2 * c] * g;
    float4 v = *(const float4*)(Y + t);
    v.x = fmaxf(v.x * g + bb, 0.0f);
    v.y = fmaxf(v.y * g + bb, 0.0f);
    v.z = fmaxf(v.z * g + bb, 0.0f);
    v.w = fmaxf(v.w * g + bb, 0.0f);
    *(float4*)(out + ((size_t)b * C + c) * N + n) = v;
}

// ---------------------------------------------------------------------------
// host driver
// ---------------------------------------------------------------------------
static inline void run_conv_bn_relu(const float* W, const float* X, float* Y,
                                    float* stats,
                                    const float* gamma, const float* beta,
                                    int M, int Ncols, int K, bool apply_ip) {
    dim3 ggrid(Ncols / 128, M / 128);
    sgemm128_kernel<<<ggrid, 256>>>(W, X, Y, M, Ncols, K);
    bn_stats_kernel<<<M, 256>>>(Y, stats, Ncols);
    if (apply_ip) {
        int total = M * Ncols;
        bn_apply_ip_kernel<<<total / 1024, 256>>>(Y, stats, gamma, beta, Ncols);
    }
}

extern "C" void kernel_launch(void* const* d_in, const int* in_sizes, int n_in,
                              void* d_out, int out_size) {
    const float* in[26];
    for (int i = 0; i < 26 && i < n_in; ++i) in[i] = (const float*)d_in[i];

    // Resolve input ordering: interleaved (setup_inputs dict) vs grouped.
    const float *xyz0, *xyz1, *xyz2, *xyz3, *f0, *f1, *f2, *f3;
    if (in_sizes[1] == 8 * 64 * 8192) {  // interleaved: xyz0,f0,xyz1,f1,...
        xyz0 = in[0]; f0 = in[1]; xyz1 = in[2]; f1 = in[3];
        xyz2 = in[4]; f2 = in[5]; xyz3 = in[6]; f3 = in[7];
    } else {  // grouped: xyz0..xyz3, f0..f3
        xyz0 = in[0]; xyz1 = in[1]; xyz2 = in[2]; xyz3 = in[3];
        f0 = in[4]; f1 = in[5]; f2 = in[6]; f3 = in[7];
    }
    const float *w00 = in[8],  *g00 = in[9],  *b00 = in[10];
    const float *w01 = in[11], *g01 = in[12], *b01 = in[13];
    const float *w10 = in[14], *g10 = in[15], *b10 = in[16];
    const float *w11 = in[17], *g11 = in[18], *b11 = in[19];
    const float *w20 = in[20], *g20 = in[21], *b20 = in[22];
    const float *w21 = in[23], *g21 = in[24], *b21 = in[25];

    float *big, *Y00, *X2, *Y20, *F2N, *X1, *Y10, *F1N, *stats;
    cudaGetSymbolAddress((void**)&big, g_big);
    cudaGetSymbolAddress((void**)&Y00, g_Y00);
    cudaGetSymbolAddress((void**)&X2, g_X2);
    cudaGetSymbolAddress((void**)&Y20, g_Y20);
    cudaGetSymbolAddress((void**)&F2N, g_F2N);
    cudaGetSymbolAddress((void**)&X1, g_X1);
    cudaGetSymbolAddress((void**)&Y10, g_Y10);
    cudaGetSymbolAddress((void**)&F1N, g_F1N);
    cudaGetSymbolAddress((void**)&stats, g_stats);

    float* X0  = big;   // 192 x 65536 during FP0 concat + conv0
    float* Y01 = big;   // 128 x 65536 after conv0 (X0 dead: conv1 reads Y00)

    float* out = (float*)d_out;
    const int B = B_SZ;

    // ---------------- FP2: xyz2 (n=512) <- xyz3 (m=128) ----------------
    {
        const int n = N2, m = N3, Cskip = 256, Cf = 512, cols = B * n;
        copy_skip_kernel<<<(B * Cskip * n) / 1024, 256>>>(f2, X2, B, Cskip, n);
        knn_interp_kernel<<<dim3(n / 256, B), 256>>>(
            xyz2, xyz3, f3, X2, n, m, Cf, Cskip, /*fb=*/Cf * m, /*fc=*/m, B);
        run_conv_bn_relu(w20, X2, Y20, stats, g20, b20, 256, cols, 768, true);
        run_conv_bn_relu(w21, Y20, F2N, stats, g21, b21, 256, cols, 256, true);
    }

    // ---------------- FP1: xyz1 (n=2048) <- xyz2 (m=512) ----------------
    {
        const int n = N1, m = N2, Cskip = 128, Cf = 256, cols = B * n;
        copy_skip_kernel<<<(B * Cskip * n) / 1024, 256>>>(f1, X1, B, Cskip, n);
        knn_interp_kernel<<<dim3(n / 256, B), 256>>>(
            xyz1, xyz2, F2N, X1, n, m, Cf, Cskip, /*fb=*/m, /*fc=*/B * m, B);
        run_conv_bn_relu(w10, X1, Y10, stats, g10, b10, 256, cols, 384, true);
        run_conv_bn_relu(w11, Y10, F1N, stats, g11, b11, 128, cols, 256, true);
    }

    // ---------------- FP0: xyz0 (n=8192) <- xyz1 (m=2048) ----------------
    {
        const int n = N0, m = N1, Cskip = 64, Cf = 128, cols = B * n;
        copy_skip_kernel<<<(B * Cskip * n) / 1024, 256>>>(f0, X0, B, Cskip, n);
        knn_interp_kernel<<<dim3(n / 256, B), 256>>>(
            xyz0, xyz1, F1N, X0, n, m, Cf, Cskip, /*fb=*/m, /*fc=*/B * m, B);
        run_conv_bn_relu(w00, X0, Y00, stats, g00, b00, 128, cols, 192, true);
        // final conv: stats then apply with transpose into d_out.
        run_conv_bn_relu(w01, Y00, Y01, stats, g01, b01, 128, cols, 128, false);
        const int total = 128 * cols;
        bn_apply_out_kernel<<<total / 1024, 256>>>(Y01, stats, g01, b01, out,
                                                   B, 128, n);
    }
}

// round 10
// speedup vs baseline: 1.0002x; 1.0002x over previous
#include <cuda_runtime.h>
#include <cstdint>

// ---------------------------------------------------------------------------
// PointNet++ decoder: 3 FP modules, each = {3-NN interp + concat skip} ->
// conv1x1+BN+ReLU -> conv1x1+BN+ReLU.
// Scratch layout: X is (C_rows, B*N cols) row-major so convs are single GEMMs
// and BN stats are per-row reductions. GEMM = fp32 SIMT, 128x128x16 tile,
// 8x8 micro-tile (FFMA-issue-bound, target ~70% of fp32 peak).
// NOTE: harness target is sm_100 (no 'a') -> no tcgen05, no kind::tf32.
// ---------------------------------------------------------------------------

#define B_SZ 8
#define N0 8192
#define N1 2048
#define N2 512
#define N3 128

// scratch buffers (device globals: allocation-free scratch).
//   g_big:   X0 (192 x 65536) during FP0 concat/conv0; then reused as Y01.
__device__ float g_big[192 * (B_SZ * N0)];   // 50.3 MB
__device__ float g_Y00[128 * (B_SZ * N0)];   // 33.6 MB
__device__ float g_X2[768 * (B_SZ * N2)];    // 12.6 MB
__device__ float g_Y20[256 * (B_SZ * N2)];   // 4.2 MB
__device__ float g_F2N[256 * (B_SZ * N2)];   // 4.2 MB
__device__ float g_X1[384 * (B_SZ * N1)];    // 25.2 MB
__device__ float g_Y10[256 * (B_SZ * N1)];   // 16.8 MB (dedicated: no overrun)
__device__ float g_F1N[128 * (B_SZ * N1)];   // 8.4 MB
__device__ float g_stats[2 * 256];           // per-channel {mean, rstd}

// ---------------------------------------------------------------------------
// copy skip features (B,C,N) -> X rows [0,C), layout (C, B*N)
// ---------------------------------------------------------------------------
__global__ void copy_skip_kernel(const float* __restrict__ src,
                                 float* __restrict__ dst,
                                 int B, int C, int N) {
    size_t t = ((size_t)blockIdx.x * blockDim.x + threadIdx.x) * 4;
    int BN = B * N;
    int c = (int)(t / BN);
    int rem = (int)(t % BN);
    int b = rem / N;
    int n = rem % N;
    *(float4*)(dst + t) =
        *(const float4*)(src + ((size_t)b * C + c) * N + n);
}

// ---------------------------------------------------------------------------
// kNN(3) + inverse-distance interpolation (channel-major feats).
// feats indexed as feats[b*fb + c*fc + j]; writes X rows [c0, c0+C)
// with column index b*n + pi (row stride = B*n).
// ---------------------------------------------------------------------------
__global__ void knn_interp_kernel(const float* __restrict__ uxyz,
                                  const float* __restrict__ kxyz,
                                  const float* __restrict__ feats,
                                  float* __restrict__ X,
                                  int n, int m, int C, int c0,
                                  int fb, int fc, int B) {
    __shared__ float skx[2048];
    __shared__ float sky[2048];
    __shared__ float skz[2048];

    const int b = blockIdx.y;
    const int pi = blockIdx.x * blockDim.x + threadIdx.x;

    for (int j = threadIdx.x; j < m; j += blockDim.x) {
        const float* p = kxyz + ((size_t)b * m + j) * 3;
        skx[j] = p[0];
        sky[j] = p[1];
        skz[j] = p[2];
    }
    __syncthreads();
    if (pi >= n) return;

    const float* up = uxyz + ((size_t)b * n + pi) * 3;
    const float ux = up[0], uy = up[1], uz = up[2];

    float d0 = 1e30f, d1 = 1e30f, d2 = 1e30f;
    int i0 = 0, i1 = 0, i2 = 0;
    for (int j = 0; j < m; ++j) {
        float dx = ux - skx[j];
        float dy = uy - sky[j];
        float dz = uz - skz[j];
        float d = dx * dx + dy * dy + dz * dz;
        if (d < d2) {
            if (d < d1) {
                d2 = d1; i2 = i1;
                if (d < d0) { d1 = d0; i1 = i0; d0 = d; i0 = j; }
                else        { d1 = d;  i1 = j; }
            } else {
                d2 = d; i2 = j;
            }
        }
    }

    float r0 = 1.0f / (d0 + 1e-8f);
    float r1 = 1.0f / (d1 + 1e-8f);
    float r2 = 1.0f / (d2 + 1e-8f);
    float rs = 1.0f / (r0 + r1 + r2);
    const float w0 = r0 * rs, w1 = r1 * rs, w2 = r2 * rs;

    const float* fbase = feats + (size_t)b * fb;
    const size_t ocol = (size_t)b * n + pi;
    const size_t rowstride = (size_t)B * n;
    float* outp = X + (size_t)c0 * rowstride + ocol;
    for (int c = 0; c < C; ++c) {
        const float* fr = fbase + (size_t)c * fc;
        outp[(size_t)c * rowstride] = w0 * fr[i0] + w1 * fr[i1] + w2 * fr[i2];
    }
}

// ---------------------------------------------------------------------------
// SGEMM: C(M x N) = A(M x K) @ B(K x N), row-major fp32.
// CTA tile 128x128x16, 256 threads, 8x8 micro-tile, register-prefetch
// double buffering of the global->shared stage.
// M in {128,256}, N % 128 == 0, K % 16 == 0 (all exact for this problem).
// ---------------------------------------------------------------------------
__global__ __launch_bounds__(256) void sgemm128_kernel(
    const float* __restrict__ A, const float* __restrict__ B,
    float* __restrict__ C, int M, int N, int K) {
    __shared__ float As[16][128];  // As[k][m] (transposed on store)
    __shared__ float Bs[16][128];  // Bs[k][n]

    const int tid = threadIdx.x;
    const int bm = blockIdx.y * 128;
    const int bn = blockIdx.x * 128;
    const int tx = tid & 15;    // micro-tile col group
    const int ty = tid >> 4;    // micro-tile row group

    // A loaders: 512 float4 per tile; thread t handles idx {t, t+256}
    //   row = idx & 127, kcol = (idx >> 7) * 4
    const int a_row = tid & 127;
    const int a_c0 = (tid >> 7) * 4;        // 0 or 4
    // B loaders: idx {t, t+256}: k = idx >> 5, col = (idx & 31) * 4
    const int b_k0 = tid >> 5;              // 0..7
    const int b_col = (tid & 31) * 4;

    const float* Ap0 = A + (size_t)(bm + a_row) * K + a_c0;
    const float* Ap1 = Ap0 + 8;
    const float* Bp0 = B + (size_t)b_k0 * N + bn + b_col;
    const float* Bp1 = Bp0 + (size_t)8 * N;

    float acc[8][8];
#pragma unroll
    for (int i = 0; i < 8; ++i)
#pragma unroll
        for (int j = 0; j < 8; ++j) acc[i][j] = 0.0f;

    // prologue: fetch tile 0 into registers
    float4 pa0 = *(const float4*)(Ap0);
    float4 pa1 = *(const float4*)(Ap1);
    float4 pb0 = *(const float4*)(Bp0);
    float4 pb1 = *(const float4*)(Bp1);

    for (int k0 = 0; k0 < K; k0 += 16) {
        // store prefetched tile to shared
        As[a_c0 + 0][a_row] = pa0.x;
        As[a_c0 + 1][a_row] = pa0.y;
        As[a_c0 + 2][a_row] = pa0.z;
        As[a_c0 + 3][a_row] = pa0.w;
        As[a_c0 + 8][a_row] = pa1.x;
        As[a_c0 + 9][a_row] = pa1.y;
        As[a_c0 + 10][a_row] = pa1.z;
        As[a_c0 + 11][a_row] = pa1.w;
        *(float4*)&Bs[b_k0][b_col] = pb0;
        *(float4*)&Bs[b_k0 + 8][b_col] = pb1;
        __syncthreads();

        // prefetch next tile
        if (k0 + 16 < K) {
            pa0 = *(const float4*)(Ap0 + k0 + 16);
            pa1 = *(const float4*)(Ap1 + k0 + 16);
            pb0 = *(const float4*)(Bp0 + (size_t)(k0 + 16) * N);
            pb1 = *(const float4*)(Bp1 + (size_t)(k0 + 16) * N);
        }

#pragma unroll
        for (int kk = 0; kk < 16; ++kk) {
            float af[8], bf[8];
            *(float4*)&af[0] = *(const float4*)&As[kk][ty * 4];
            *(float4*)&af[4] = *(const float4*)&As[kk][ty * 4 + 64];
            *(float4*)&bf[0] = *(const float4*)&Bs[kk][tx * 4];
            *(float4*)&bf[4] = *(const float4*)&Bs[kk][tx * 4 + 64];
#pragma unroll
            for (int i = 0; i < 8; ++i)
#pragma unroll
                for (int j = 0; j < 8; ++j)
                    acc[i][j] = fmaf(af[i], bf[j], acc[i][j]);
        }
        __syncthreads();
    }

    // epilogue: rows bm + ty*4 + {0..3} and +64; cols bn + tx*4 (+64)
#pragma unroll
    for (int ih = 0; ih < 2; ++ih) {
#pragma unroll
        for (int i = 0; i < 4; ++i) {
            const int row = bm + ih * 64 + ty * 4 + i;
            float* cp = C + (size_t)row * N + bn;
            *(float4*)(cp + tx * 4) =
                make_float4(acc[ih * 4 + i][0], acc[ih * 4 + i][1],
                            acc[ih * 4 + i][2], acc[ih * 4 + i][3]);
            *(float4*)(cp + tx * 4 + 64) =
                make_float4(acc[ih * 4 + i][4], acc[ih * 4 + i][5],
                            acc[ih * 4 + i][6], acc[ih * 4 + i][7]);
        }
    }
}

// ---------------------------------------------------------------------------
// BN batch stats: per row (channel) of Y (C x Ncols): mean & rsqrt(var+eps)
// ---------------------------------------------------------------------------
__global__ void bn_stats_kernel(const float* __restrict__ Y,
                                float* __restrict__ stats, int Ncols) {
    const int c = blockIdx.x;
    const float* row = Y + (size_t)c * Ncols;
    float s = 0.0f, s2 = 0.0f;
    for (int i = threadIdx.x * 4; i < Ncols; i += blockDim.x * 4) {
        float4 v = *(const float4*)(row + i);
        s += v.x + v.y + v.z + v.w;
        s2 += v.x * v.x + v.y * v.y + v.z * v.z + v.w * v.w;
    }
#pragma unroll
    for (int o = 16; o; o >>= 1) {
        s += __shfl_down_sync(0xFFFFFFFFu, s, o);
        s2 += __shfl_down_sync(0xFFFFFFFFu, s2, o);
    }
    __shared__ float ws[8], ws2[8];
    const int w = threadIdx.x >> 5, l = threadIdx.x & 31;
    if (l == 0) { ws[w] = s; ws2[w] = s2; }
    __syncthreads();
    if (threadIdx.x == 0) {
        float S = 0.0f, S2 = 0.0f;
        const int nw = blockDim.x >> 5;
        for (int i = 0; i < nw; ++i) { S += ws[i]; S2 += ws2[i]; }
        const float inv = 1.0f / (float)Ncols;
        const float mean = S * inv;
        const float var = S2 * inv - mean * mean;
        stats[2 * c] = mean;
        stats[2 * c + 1] = rsqrtf(var + 1e-5f);
    }
}

// ---------------------------------------------------------------------------
// BN apply + ReLU, in place on (C x Ncols)
// ---------------------------------------------------------------------------
__global__ void bn_apply_ip_kernel(float* __restrict__ Y,
                                   const float* __restrict__ stats,
                                   const float* __restrict__ gamma,
                                   const float* __restrict__ beta,
                                   int Ncols) {
    size_t t = ((size_t)blockIdx.x * blockDim.x + threadIdx.x) * 4;
    const int c = (int)(t / Ncols);
    const float g = gamma[c] * stats[2 * c + 1];
    const float b = beta[c] - stats[2 * c] * g;
    float4 v = *(float4*)(Y + t);
    v.x = fmaxf(v.x * g + b, 0.0f);
    v.y = fmaxf(v.y * g + b, 0.0f);
    v.z = fmaxf(v.z * g + b, 0.0f);
    v.w = fmaxf(v.w * g + b, 0.0f);
    *(float4*)(Y + t) = v;
}

// ---------------------------------------------------------------------------
// BN apply + ReLU, (C, B*N) -> out (B,C,N)
// ---------------------------------------------------------------------------
__global__ void bn_apply_out_kernel(const float* __restrict__ Y,
                                    const float* __restrict__ stats,
                                    const float* __restrict__ gamma,
                                    const float* __restrict__ beta,
                                    float* __restrict__ out,
                                    int B, int C, int N) {
    size_t t = ((size_t)blockIdx.x * blockDim.x + threadIdx.x) * 4;
    const int BN = B * N;
    const int c = (int)(t / BN);
    const int rem = (int)(t % BN);
    const int b = rem / N;
    const int n = rem % N;
    const float g = gamma[c] * stats[2 * c + 1];
    const float bb = beta[c] - stats[2 * c] * g;
    float4 v = *(const float4*)(Y + t);
    v.x = fmaxf(v.x * g + bb, 0.0f);
    v.y = fmaxf(v.y * g + bb, 0.0f);
    v.z = fmaxf(v.z * g + bb, 0.0f);
    v.w = fmaxf(v.w * g + bb, 0.0f);
    *(float4*)(out + ((size_t)b * C + c) * N + n) = v;
}

// ---------------------------------------------------------------------------
// host driver
// ---------------------------------------------------------------------------
static inline void run_conv_bn_relu(const float* W, const float* X, float* Y,
                                    float* stats,
                                    const float* gamma, const float* beta,
                                    int M, int Ncols, int K, bool apply_ip) {
    dim3 ggrid(Ncols / 128, M / 128);
    sgemm128_kernel<<<ggrid, 256>>>(W, X, Y, M, Ncols, K);
    bn_stats_kernel<<<M, 256>>>(Y, stats, Ncols);
    if (apply_ip) {
        int total = M * Ncols;
        bn_apply_ip_kernel<<<total / 1024, 256>>>(Y, stats, gamma, beta, Ncols);
    }
}

extern "C" void kernel_launch(void* const* d_in, const int* in_sizes, int n_in,
                              void* d_out, int out_size) {
    const float* in[26];
    for (int i = 0; i < 26 && i < n_in; ++i) in[i] = (const float*)d_in[i];

    // Resolve input ordering: interleaved (setup_inputs dict) vs grouped.
    const float *xyz0, *xyz1, *xyz2, *xyz3, *f0, *f1, *f2, *f3;
    if (in_sizes[1] == 8 * 64 * 8192) {  // interleaved: xyz0,f0,xyz1,f1,...
        xyz0 = in[0]; f0 = in[1]; xyz1 = in[2]; f1 = in[3];
        xyz2 = in[4]; f2 = in[5]; xyz3 = in[6]; f3 = in[7];
    } else {  // grouped: xyz0..xyz3, f0..f3
        xyz0 = in[0]; xyz1 = in[1]; xyz2 = in[2]; xyz3 = in[3];
        f0 = in[4]; f1 = in[5]; f2 = in[6]; f3 = in[7];
    }
    const float *w00 = in[8],  *g00 = in[9],  *b00 = in[10];
    const float *w01 = in[11], *g01 = in[12], *b01 = in[13];
    const float *w10 = in[14], *g10 = in[15], *b10 = in[16];
    const float *w11 = in[17], *g11 = in[18], *b11 = in[19];
    const float *w20 = in[20], *g20 = in[21], *b20 = in[22];
    const float *w21 = in[23], *g21 = in[24], *b21 = in[25];

    float *big, *Y00, *X2, *Y20, *F2N, *X1, *Y10, *F1N, *stats;
    cudaGetSymbolAddress((void**)&big, g_big);
    cudaGetSymbolAddress((void**)&Y00, g_Y00);
    cudaGetSymbolAddress((void**)&X2, g_X2);
    cudaGetSymbolAddress((void**)&Y20, g_Y20);
    cudaGetSymbolAddress((void**)&F2N, g_F2N);
    cudaGetSymbolAddress((void**)&X1, g_X1);
    cudaGetSymbolAddress((void**)&Y10, g_Y10);
    cudaGetSymbolAddress((void**)&F1N, g_F1N);
    cudaGetSymbolAddress((void**)&stats, g_stats);

    float* X0  = big;   // 192 x 65536 during FP0 concat + conv0
    float* Y01 = big;   // 128 x 65536 after conv0 (X0 dead: conv1 reads Y00)

    float* out = (float*)d_out;
    const int B = B_SZ;

    // ---------------- FP2: xyz2 (n=512) <- xyz3 (m=128) ----------------
    {
        const int n = N2, m = N3, Cskip = 256, Cf = 512, cols = B * n;
        copy_skip_kernel<<<(B * Cskip * n) / 1024, 256>>>(f2, X2, B, Cskip, n);
        knn_interp_kernel<<<dim3(n / 256, B), 256>>>(
            xyz2, xyz3, f3, X2, n, m, Cf, Cskip, /*fb=*/Cf * m, /*fc=*/m, B);
        run_conv_bn_relu(w20, X2, Y20, stats, g20, b20, 256, cols, 768, true);
        run_conv_bn_relu(w21, Y20, F2N, stats, g21, b21, 256, cols, 256, true);
    }

    // ---------------- FP1: xyz1 (n=2048) <- xyz2 (m=512) ----------------
    {
        const int n = N1, m = N2, Cskip = 128, Cf = 256, cols = B * n;
        copy_skip_kernel<<<(B * Cskip * n) / 1024, 256>>>(f1, X1, B, Cskip, n);
        knn_interp_kernel<<<dim3(n / 256, B), 256>>>(
            xyz1, xyz2, F2N, X1, n, m, Cf, Cskip, /*fb=*/m, /*fc=*/B * m, B);
        run_conv_bn_relu(w10, X1, Y10, stats, g10, b10, 256, cols, 384, true);
        run_conv_bn_relu(w11, Y10, F1N, stats, g11, b11, 128, cols, 256, true);
    }

    // ---------------- FP0: xyz0 (n=8192) <- xyz1 (m=2048) ----------------
    {
        const int n = N0, m = N1, Cskip = 64, Cf = 128, cols = B * n;
        copy_skip_kernel<<<(B * Cskip * n) / 1024, 256>>>(f0, X0, B, Cskip, n);
        knn_interp_kernel<<<dim3(n / 256, B), 256>>>(
            xyz0, xyz1, F1N, X0, n, m, Cf, Cskip, /*fb=*/m, /*fc=*/B * m, B);
        run_conv_bn_relu(w00, X0, Y00, stats, g00, b00, 128, cols, 192, true);
        // final conv: stats then apply with transpose into d_out.
        run_conv_bn_relu(w01, Y00, Y01, stats, g01, b01, 128, cols, 128, false);
        const int total = 128 * cols;
        bn_apply_out_kernel<<<total / 1024, 256>>>(Y01, stats, g01, b01, out,
                                                   B, 128, n);
    }
}

// round 11
// speedup vs baseline: 1.0635x; 1.0632x over previous
#include <cuda_runtime.h>
#include <cstdint>

// ---------------------------------------------------------------------------
// PointNet++ decoder. Conv1x1 GEMMs on the fp32 pipe using Blackwell packed
// fma.rn.f32x2 (FFMA2: 2 FMA per issue slot -> 2x the FFMA-3reg ceiling).
// Layout: X is (C_rows, B*N cols) row-major; convs are single GEMMs; BN stats
// are row reductions (split 8-way + atomics).
// Target is sm_100 (no 'a'): no tcgen05, no kind::tf32.
// ---------------------------------------------------------------------------

#define B_SZ 8
#define N0 8192
#define N1 2048
#define N2 512
#define N3 128

__device__ float g_big[192 * (B_SZ * N0)];   // X0; later aliased as Y01
__device__ float g_Y00[128 * (B_SZ * N0)];
__device__ float g_X2[768 * (B_SZ * N2)];
__device__ float g_Y20[256 * (B_SZ * N2)];
__device__ float g_F2N[256 * (B_SZ * N2)];
__device__ float g_X1[384 * (B_SZ * N1)];
__device__ float g_Y10[256 * (B_SZ * N1)];
__device__ float g_F1N[128 * (B_SZ * N1)];
__device__ float g_sums[6 * 512];  // per layer: [0,256)=sum, [256,512)=sumsq

// ---------------- packed f32x2 helpers ----------------
__device__ __forceinline__ unsigned long long pack2(float x, float y) {
    unsigned long long r;
    asm("mov.b64 %0, {%1, %2};" : "=l"(r) : "f"(x), "f"(y));
    return r;
}
__device__ __forceinline__ unsigned long long fma2(unsigned long long a,
                                                   unsigned long long b,
                                                   unsigned long long c) {
    unsigned long long d;
    asm("fma.rn.f32x2 %0, %1, %2, %3;" : "=l"(d) : "l"(a), "l"(b), "l"(c));
    return d;
}

// ---------------------------------------------------------------------------
// copy skip features (B,C,N) -> X rows [0,C), layout (C, B*N)
// ---------------------------------------------------------------------------
__global__ void copy_skip_kernel(const float* __restrict__ src,
                                 float* __restrict__ dst,
                                 int B, int C, int N) {
    size_t t = ((size_t)blockIdx.x * blockDim.x + threadIdx.x) * 4;
    int BN = B * N;
    int c = (int)(t / BN);
    int rem = (int)(t % BN);
    int b = rem / N;
    int n = rem % N;
    *(float4*)(dst + t) =
        *(const float4*)(src + ((size_t)b * C + c) * N + n);
}

// ---------------------------------------------------------------------------
// kNN(3) + inverse-distance interpolation (channel-major feats).
// ---------------------------------------------------------------------------
__global__ void knn_interp_kernel(const float* __restrict__ uxyz,
                                  const float* __restrict__ kxyz,
                                  const float* __restrict__ feats,
                                  float* __restrict__ X,
                                  int n, int m, int C, int c0,
                                  int fb, int fc, int B) {
    __shared__ float skx[2048];
    __shared__ float sky[2048];
    __shared__ float skz[2048];

    const int b = blockIdx.y;
    const int pi = blockIdx.x * blockDim.x + threadIdx.x;

    for (int j = threadIdx.x; j < m; j += blockDim.x) {
        const float* p = kxyz + ((size_t)b * m + j) * 3;
        skx[j] = p[0];
        sky[j] = p[1];
        skz[j] = p[2];
    }
    __syncthreads();
    if (pi >= n) return;

    const float* up = uxyz + ((size_t)b * n + pi) * 3;
    const float ux = up[0], uy = up[1], uz = up[2];

    float d0 = 1e30f, d1 = 1e30f, d2 = 1e30f;
    int i0 = 0, i1 = 0, i2 = 0;
    for (int j = 0; j < m; ++j) {
        float dx = ux - skx[j];
        float dy = uy - sky[j];
        float dz = uz - skz[j];
        float d = dx * dx + dy * dy + dz * dz;
        if (d < d2) {
            if (d < d1) {
                d2 = d1; i2 = i1;
                if (d < d0) { d1 = d0; i1 = i0; d0 = d; i0 = j; }
                else        { d1 = d;  i1 = j; }
            } else {
                d2 = d; i2 = j;
            }
        }
    }

    float r0 = 1.0f / (d0 + 1e-8f);
    float r1 = 1.0f / (d1 + 1e-8f);
    float r2 = 1.0f / (d2 + 1e-8f);
    float rs = 1.0f / (r0 + r1 + r2);
    const float w0 = r0 * rs, w1 = r1 * rs, w2 = r2 * rs;

    const float* fbase = feats + (size_t)b * fb;
    const size_t ocol = (size_t)b * n + pi;
    const size_t rowstride = (size_t)B * n;
    float* outp = X + (size_t)c0 * rowstride + ocol;
    for (int c = 0; c < C; ++c) {
        const float* fr = fbase + (size_t)c * fc;
        outp[(size_t)c * rowstride] = w0 * fr[i0] + w1 * fr[i1] + w2 * fr[i2];
    }
}

// ---------------------------------------------------------------------------
// SGEMM with packed f32x2 FMA: C(M x N) = A(M x K) @ B(K x N), row-major.
// CTA tile 128 x BN x 16 (BN = 128 or 64), 256 threads, micro-tile 8 x (BN/16),
// accumulators are f32x2 pairs along N. Register-prefetch double buffering.
// M in {128,256}, N % BN == 0, K % 16 == 0 (exact for this problem).
// ---------------------------------------------------------------------------
template <int BN>
__global__ __launch_bounds__(256) void sgemm_f32x2_kernel(
    const float* __restrict__ A, const float* __restrict__ B,
    float* __restrict__ C, int M, int N, int K) {
    constexpr int NP = BN / 32;  // f32x2 pairs per thread along N (4 or 2)
    __shared__ float As[16][128];  // As[k][m]
    __shared__ float Bs[16][BN];   // Bs[k][n]

    const int tid = threadIdx.x;
    const int bm = blockIdx.y * 128;
    const int bn = blockIdx.x * BN;
    const int tx = tid & 15;    // col group: covers tx*4 (+64 when BN=128)
    const int ty = tid >> 4;    // row group: covers ty*4 + {0..3}, +64

    // A loaders: 512 float4/tile; thread t -> {t, t+256}
    const int a_row = tid & 127;
    const int a_c0 = (tid >> 7) * 4;  // 0 or 4
    const float* Ap0 = A + (size_t)(bm + a_row) * K + a_c0;
    const float* Ap1 = Ap0 + 8;

    // B loaders
    int b_k0, b_col;
    if (BN == 128) { b_k0 = tid >> 5; b_col = (tid & 31) * 4; }  // 2 ld/thread
    else           { b_k0 = tid >> 4; b_col = (tid & 15) * 4; }  // 1 ld/thread
    const float* Bp0 = B + (size_t)b_k0 * N + bn + b_col;
    const float* Bp1 = Bp0 + (size_t)8 * N;  // only used when BN == 128

    unsigned long long acc[8][NP];
#pragma unroll
    for (int i = 0; i < 8; ++i)
#pragma unroll
        for (int j = 0; j < NP; ++j) acc[i][j] = 0ull;

    // prologue: fetch tile 0
    float4 pa0 = *(const float4*)(Ap0);
    float4 pa1 = *(const float4*)(Ap1);
    float4 pb0 = *(const float4*)(Bp0);
    float4 pb1;
    if (BN == 128) pb1 = *(const float4*)(Bp1);

    for (int k0 = 0; k0 < K; k0 += 16) {
        As[a_c0 + 0][a_row] = pa0.x;
        As[a_c0 + 1][a_row] = pa0.y;
        As[a_c0 + 2][a_row] = pa0.z;
        As[a_c0 + 3][a_row] = pa0.w;
        As[a_c0 + 8][a_row] = pa1.x;
        As[a_c0 + 9][a_row] = pa1.y;
        As[a_c0 + 10][a_row] = pa1.z;
        As[a_c0 + 11][a_row] = pa1.w;
        *(float4*)&Bs[b_k0][b_col] = pb0;
        if (BN == 128) *(float4*)&Bs[b_k0 + 8][b_col] = pb1;
        __syncthreads();

        if (k0 + 16 < K) {
            pa0 = *(const float4*)(Ap0 + k0 + 16);
            pa1 = *(const float4*)(Ap1 + k0 + 16);
            pb0 = *(const float4*)(Bp0 + (size_t)(k0 + 16) * N);
            if (BN == 128) pb1 = *(const float4*)(Bp1 + (size_t)(k0 + 16) * N);
        }

#pragma unroll
        for (int kk = 0; kk < 16; ++kk) {
            float af[8];
            *(float4*)&af[0] = *(const float4*)&As[kk][ty * 4];
            *(float4*)&af[4] = *(const float4*)&As[kk][ty * 4 + 64];
            unsigned long long bp[NP];
            {
                ulonglong2 t0 = *(const ulonglong2*)&Bs[kk][tx * 4];
                bp[0] = t0.x; bp[1] = t0.y;
                if (BN == 128) {
                    ulonglong2 t1 = *(const ulonglong2*)&Bs[kk][tx * 4 + 64];
                    bp[2] = t1.x; bp[3] = t1.y;
                }
            }
#pragma unroll
            for (int i = 0; i < 8; ++i) {
                unsigned long long aa = pack2(af[i], af[i]);
#pragma unroll
                for (int j = 0; j < NP; ++j)
                    acc[i][j] = fma2(aa, bp[j], acc[i][j]);
            }
        }
        __syncthreads();
    }

    // epilogue: acc[i][0..1] -> cols bn+tx*4..+3; acc[i][2..3] -> +64
#pragma unroll
    for (int ih = 0; ih < 2; ++ih) {
#pragma unroll
        for (int i = 0; i < 4; ++i) {
            const int row = bm + ih * 64 + ty * 4 + i;
            float* cp = C + (size_t)row * N + bn;
            ulonglong2 v0;
            v0.x = acc[ih * 4 + i][0];
            v0.y = acc[ih * 4 + i][1];
            *(ulonglong2*)(cp + tx * 4) = v0;
            if (BN == 128) {
                ulonglong2 v1;
                v1.x = acc[ih * 4 + i][2];
                v1.y = acc[ih * 4 + i][3];
                *(ulonglong2*)(cp + tx * 4 + 64) = v1;
            }
        }
    }
}

// ---------------------------------------------------------------------------
// BN stats, parallel: grid (C, nchunk); atomicAdd partial {sum, sumsq}.
// sums layout: sums[c] = sum, sums[256 + c] = sumsq.
// ---------------------------------------------------------------------------
__global__ void zero_sums_kernel(float* sums) {
    sums[blockIdx.x * 256 + threadIdx.x] = 0.0f;
}

__global__ void bn_stats_part_kernel(const float* __restrict__ Y,
                                     float* __restrict__ sums, int Ncols) {
    const int c = blockIdx.x;
    const int len = Ncols / gridDim.y;
    const float* row = Y + (size_t)c * Ncols + (size_t)blockIdx.y * len;
    float s = 0.0f, s2 = 0.0f;
    for (int i = threadIdx.x * 4; i < len; i += blockDim.x * 4) {
        float4 v = *(const float4*)(row + i);
        s += v.x + v.y + v.z + v.w;
        s2 += v.x * v.x + v.y * v.y + v.z * v.z + v.w * v.w;
    }
#pragma unroll
    for (int o = 16; o; o >>= 1) {
        s += __shfl_down_sync(0xFFFFFFFFu, s, o);
        s2 += __shfl_down_sync(0xFFFFFFFFu, s2, o);
    }
    __shared__ float ws[8], ws2[8];
    const int w = threadIdx.x >> 5, l = threadIdx.x & 31;
    if (l == 0) { ws[w] = s; ws2[w] = s2; }
    __syncthreads();
    if (threadIdx.x == 0) {
        float S = 0.0f, S2 = 0.0f;
        const int nw = blockDim.x >> 5;
        for (int i = 0; i < nw; ++i) { S += ws[i]; S2 += ws2[i]; }
        atomicAdd(&sums[c], S);
        atomicAdd(&sums[256 + c], S2);
    }
}

// ---------------------------------------------------------------------------
// BN apply + ReLU, in place on (C x Ncols); mean/rstd from raw sums
// ---------------------------------------------------------------------------
__global__ void bn_apply_ip_kernel(float* __restrict__ Y,
                                   const float* __restrict__ sums,
                                   const float* __restrict__ gamma,
                                   const float* __restrict__ beta,
                                   int Ncols, float invN) {
    size_t t = ((size_t)blockIdx.x * blockDim.x + threadIdx.x) * 4;
    const int c = (int)(t / Ncols);
    const float mean = sums[c] * invN;
    const float var = sums[256 + c] * invN - mean * mean;
    const float g = gamma[c] * rsqrtf(var + 1e-5f);
    const float b = beta[c] - mean * g;
    float4 v = *(float4*)(Y + t);
    v.x = fmaxf(v.x * g + b, 0.0f);
    v.y = fmaxf(v.y * g + b, 0.0f);
    v.z = fmaxf(v.z * g + b, 0.0f);
    v.w = fmaxf(v.w * g + b, 0.0f);
    *(float4*)(Y + t) = v;
}

// ---------------------------------------------------------------------------
// BN apply + ReLU, (C, B*N) -> out (B,C,N)
// ---------------------------------------------------------------------------
__global__ void bn_apply_out_kernel(const float* __restrict__ Y,
                                    const float* __restrict__ sums,
                                    const float* __restrict__ gamma,
                                    const float* __restrict__ beta,
                                    float* __restrict__ out,
                                    int B, int C, int N, float invN) {
    size_t t = ((size_t)blockIdx.x * blockDim.x + threadIdx.x) * 4;
    const int BN = B * N;
    const int c = (int)(t / BN);
    const int rem = (int)(t % BN);
    const int b = rem / N;
    const int n = rem % N;
    const float mean = sums[c] * invN;
    const float var = sums[256 + c] * invN - mean * mean;
    const float g = gamma[c] * rsqrtf(var + 1e-5f);
    const float bb = beta[c] - mean * g;
    float4 v = *(const float4*)(Y + t);
    v.x = fmaxf(v.x * g + bb, 0.0f);
    v.y = fmaxf(v.y * g + bb, 0.0f);
    v.z = fmaxf(v.z * g + bb, 0.0f);
    v.w = fmaxf(v.w * g + bb, 0.0f);
    *(float4*)(out + ((size_t)b * C + c) * N + n) = v;
}

// ---------------------------------------------------------------------------
// host driver
// ---------------------------------------------------------------------------
static inline void run_conv_bn_relu(const float* W, const float* X, float* Y,
                                    float* sums,
                                    const float* gamma, const float* beta,
                                    int M, int Ncols, int K, int bn_tile,
                                    bool apply_ip) {
    if (bn_tile == 64) {
        dim3 g(Ncols / 64, M / 128);
        sgemm_f32x2_kernel<64><<<g, 256>>>(W, X, Y, M, Ncols, K);
    } else {
        dim3 g(Ncols / 128, M / 128);
        sgemm_f32x2_kernel<128><<<g, 256>>>(W, X, Y, M, Ncols, K);
    }
    bn_stats_part_kernel<<<dim3(M, 8), 256>>>(Y, sums, Ncols);
    if (apply_ip) {
        int total = M * Ncols;
        bn_apply_ip_kernel<<<total / 1024, 256>>>(Y, sums, gamma, beta, Ncols,
                                                  1.0f / (float)Ncols);
    }
}

extern "C" void kernel_launch(void* const* d_in, const int* in_sizes, int n_in,
                              void* d_out, int out_size) {
    const float* in[26];
    for (int i = 0; i < 26 && i < n_in; ++i) in[i] = (const float*)d_in[i];

    const float *xyz0, *xyz1, *xyz2, *xyz3, *f0, *f1, *f2, *f3;
    if (in_sizes[1] == 8 * 64 * 8192) {  // interleaved: xyz0,f0,xyz1,f1,...
        xyz0 = in[0]; f0 = in[1]; xyz1 = in[2]; f1 = in[3];
        xyz2 = in[4]; f2 = in[5]; xyz3 = in[6]; f3 = in[7];
    } else {  // grouped
        xyz0 = in[0]; xyz1 = in[1]; xyz2 = in[2]; xyz3 = in[3];
        f0 = in[4]; f1 = in[5]; f2 = in[6]; f3 = in[7];
    }
    const float *w00 = in[8],  *g00 = in[9],  *b00 = in[10];
    const float *w01 = in[11], *g01 = in[12], *b01 = in[13];
    const float *w10 = in[14], *g10 = in[15], *b10 = in[16];
    const float *w11 = in[17], *g11 = in[18], *b11 = in[19];
    const float *w20 = in[20], *g20 = in[21], *b20 = in[22];
    const float *w21 = in[23], *g21 = in[24], *b21 = in[25];

    float *big, *Y00, *X2, *Y20, *F2N, *X1, *Y10, *F1N, *sums;
    cudaGetSymbolAddress((void**)&big, g_big);
    cudaGetSymbolAddress((void**)&Y00, g_Y00);
    cudaGetSymbolAddress((void**)&X2, g_X2);
    cudaGetSymbolAddress((void**)&Y20, g_Y20);
    cudaGetSymbolAddress((void**)&F2N, g_F2N);
    cudaGetSymbolAddress((void**)&X1, g_X1);
    cudaGetSymbolAddress((void**)&Y10, g_Y10);
    cudaGetSymbolAddress((void**)&F1N, g_F1N);
    cudaGetSymbolAddress((void**)&sums, g_sums);

    float* X0  = big;   // 192 x 65536 during FP0 concat + conv0
    float* Y01 = big;   // 128 x 65536 after conv0 (X0 dead: conv1 reads Y00)

    float* out = (float*)d_out;
    const int B = B_SZ;

    zero_sums_kernel<<<12, 256>>>(sums);

    // ---------------- FP2: xyz2 (n=512) <- xyz3 (m=128) ----------------
    {
        const int n = N2, m = N3, Cskip = 256, Cf = 512, cols = B * n;
        copy_skip_kernel<<<(B * Cskip * n) / 1024, 256>>>(f2, X2, B, Cskip, n);
        knn_interp_kernel<<<dim3(n / 256, B), 256>>>(
            xyz2, xyz3, f3, X2, n, m, Cf, Cskip, /*fb=*/Cf * m, /*fc=*/m, B);
        run_conv_bn_relu(w20, X2, Y20, sums + 0 * 512, g20, b20,
                         256, cols, 768, 64, true);
        run_conv_bn_relu(w21, Y20, F2N, sums + 1 * 512, g21, b21,
                         256, cols, 256, 64, true);
    }

    // ---------------- FP1: xyz1 (n=2048) <- xyz2 (m=512) ----------------
    {
        const int n = N1, m = N2, Cskip = 128, Cf = 256, cols = B * n;
        copy_skip_kernel<<<(B * Cskip * n) / 1024, 256>>>(f1, X1, B, Cskip, n);
        knn_interp_kernel<<<dim3(n / 256, B), 256>>>(
            xyz1, xyz2, F2N, X1, n, m, Cf, Cskip, /*fb=*/m, /*fc=*/B * m, B);
        run_conv_bn_relu(w10, X1, Y10, sums + 2 * 512, g10, b10,
                         256, cols, 384, 128, true);
        run_conv_bn_relu(w11, Y10, F1N, sums + 3 * 512, g11, b11,
                         128, cols, 256, 128, true);
    }

    // ---------------- FP0: xyz0 (n=8192) <- xyz1 (m=2048) ----------------
    {
        const int n = N0, m = N1, Cskip = 64, Cf = 128, cols = B * n;
        copy_skip_kernel<<<(B * Cskip * n) / 1024, 256>>>(f0, X0, B, Cskip, n);
        knn_interp_kernel<<<dim3(n / 256, B), 256>>>(
            xyz0, xyz1, F1N, X0, n, m, Cf, Cskip, /*fb=*/m, /*fc=*/B * m, B);
        run_conv_bn_relu(w00, X0, Y00, sums + 4 * 512, g00, b00,
                         128, cols, 192, 128, true);
        run_conv_bn_relu(w01, Y00, Y01, sums + 5 * 512, g01, b01,
                         128, cols, 128, 128, false);
        const int total = 128 * cols;
        bn_apply_out_kernel<<<total / 1024, 256>>>(Y01, sums + 5 * 512, g01,
                                                   b01, out, B, 128, n,
                                                   1.0f / (float)cols);
    }
}

// round 13
// speedup vs baseline: 1.0659x; 1.0023x over previous
#include <cuda_runtime.h>
#include <cstdint>

// ---------------------------------------------------------------------------
// PointNet++ decoder. Conv1x1 GEMMs on the fp32 pipe using Blackwell packed
// fma.rn.f32x2 (FFMA2: 2 FMA per issue slot -> 2x the FFMA-3reg ceiling).
// Layout: X is (C_rows, B*N cols) row-major; convs are single GEMMs; BN stats
// are row reductions (split 8-way + atomics).
// Target is sm_100 (no 'a'): no tcgen05, no kind::tf32.
// ---------------------------------------------------------------------------

#define B_SZ 8
#define N0 8192
#define N1 2048
#define N2 512
#define N3 128

__device__ float g_big[192 * (B_SZ * N0)];   // X0; later aliased as Y01
__device__ float g_Y00[128 * (B_SZ * N0)];
__device__ float g_X2[768 * (B_SZ * N2)];
__device__ float g_Y20[256 * (B_SZ * N2)];
__device__ float g_F2N[256 * (B_SZ * N2)];
__device__ float g_X1[384 * (B_SZ * N1)];
__device__ float g_Y10[256 * (B_SZ * N1)];
__device__ float g_F1N[128 * (B_SZ * N1)];
__device__ float g_sums[6 * 512];  // per layer: [0,256)=sum, [256,512)=sumsq

// ---------------- packed f32x2 helpers ----------------
__device__ __forceinline__ unsigned long long pack2(float x, float y) {
    unsigned long long r;
    asm("mov.b64 %0, {%1, %2};" : "=l"(r) : "f"(x), "f"(y));
    return r;
}
__device__ __forceinline__ unsigned long long fma2(unsigned long long a,
                                                   unsigned long long b,
                                                   unsigned long long c) {
    unsigned long long d;
    asm("fma.rn.f32x2 %0, %1, %2, %3;" : "=l"(d) : "l"(a), "l"(b), "l"(c));
    return d;
}

// ---------------------------------------------------------------------------
// copy skip features (B,C,N) -> X rows [0,C), layout (C, B*N)
// ---------------------------------------------------------------------------
__global__ void copy_skip_kernel(const float* __restrict__ src,
                                 float* __restrict__ dst,
                                 int B, int C, int N) {
    size_t t = ((size_t)blockIdx.x * blockDim.x + threadIdx.x) * 4;
    int BN = B * N;
    int c = (int)(t / BN);
    int rem = (int)(t % BN);
    int b = rem / N;
    int n = rem % N;
    *(float4*)(dst + t) =
        *(const float4*)(src + ((size_t)b * C + c) * N + n);
}

// ---------------------------------------------------------------------------
// kNN(3) + inverse-distance interpolation (channel-major feats).
// ---------------------------------------------------------------------------
__global__ void knn_interp_kernel(const float* __restrict__ uxyz,
                                  const float* __restrict__ kxyz,
                                  const float* __restrict__ feats,
                                  float* __restrict__ X,
                                  int n, int m, int C, int c0,
                                  int fb, int fc, int B) {
    __shared__ float skx[2048];
    __shared__ float sky[2048];
    __shared__ float skz[2048];

    const int b = blockIdx.y;
    const int pi = blockIdx.x * blockDim.x + threadIdx.x;

    for (int j = threadIdx.x; j < m; j += blockDim.x) {
        const float* p = kxyz + ((size_t)b * m + j) * 3;
        skx[j] = p[0];
        sky[j] = p[1];
        skz[j] = p[2];
    }
    __syncthreads();
    if (pi >= n) return;

    const float* up = uxyz + ((size_t)b * n + pi) * 3;
    const float ux = up[0], uy = up[1], uz = up[2];

    float d0 = 1e30f, d1 = 1e30f, d2 = 1e30f;
    int i0 = 0, i1 = 0, i2 = 0;
    for (int j = 0; j < m; ++j) {
        float dx = ux - skx[j];
        float dy = uy - sky[j];
        float dz = uz - skz[j];
        float d = dx * dx + dy * dy + dz * dz;
        if (d < d2) {
            if (d < d1) {
                d2 = d1; i2 = i1;
                if (d < d0) { d1 = d0; i1 = i0; d0 = d; i0 = j; }
                else        { d1 = d;  i1 = j; }
            } else {
                d2 = d; i2 = j;
            }
        }
    }

    float r0 = 1.0f / (d0 + 1e-8f);
    float r1 = 1.0f / (d1 + 1e-8f);
    float r2 = 1.0f / (d2 + 1e-8f);
    float rs = 1.0f / (r0 + r1 + r2);
    const float w0 = r0 * rs, w1 = r1 * rs, w2 = r2 * rs;

    const float* fbase = feats + (size_t)b * fb;
    const size_t ocol = (size_t)b * n + pi;
    const size_t rowstride = (size_t)B * n;
    float* outp = X + (size_t)c0 * rowstride + ocol;
    for (int c = 0; c < C; ++c) {
        const float* fr = fbase + (size_t)c * fc;
        outp[(size_t)c * rowstride] = w0 * fr[i0] + w1 * fr[i1] + w2 * fr[i2];
    }
}

// ---------------------------------------------------------------------------
// SGEMM with packed f32x2 FMA: C(M x N) = A(M x K) @ B(K x N), row-major.
// CTA tile 128 x BN x 16 (BN = 128 or 64), 256 threads, micro-tile 8 x (BN/16),
// accumulators are f32x2 pairs along N. Register-prefetch double buffering.
// M in {128,256}, N % BN == 0, K % 16 == 0 (exact for this problem).
// ---------------------------------------------------------------------------
template <int BN>
__global__ __launch_bounds__(256) void sgemm_f32x2_kernel(
    const float* __restrict__ A, const float* __restrict__ B,
    float* __restrict__ C, int M, int N, int K) {
    constexpr int NP = BN / 32;  // f32x2 pairs per thread along N (4 or 2)
    __shared__ float As[16][128];  // As[k][m]
    __shared__ float Bs[16][BN];   // Bs[k][n]

    const int tid = threadIdx.x;
    const int bm = blockIdx.y * 128;
    const int bn = blockIdx.x * BN;
    const int tx = tid & 15;    // col group: covers tx*4 (+64 when BN=128)
    const int ty = tid >> 4;    // row group: covers ty*4 + {0..3}, +64

    // A loaders: 512 float4/tile; thread t -> {t, t+256}
    const int a_row = tid & 127;
    const int a_c0 = (tid >> 7) * 4;  // 0 or 4
    const float* Ap0 = A + (size_t)(bm + a_row) * K + a_c0;
    const float* Ap1 = Ap0 + 8;

    // B loaders
    int b_k0, b_col;
    if (BN == 128) { b_k0 = tid >> 5; b_col = (tid & 31) * 4; }  // 2 ld/thread
    else           { b_k0 = tid >> 4; b_col = (tid & 15) * 4; }  // 1 ld/thread
    const float* Bp0 = B + (size_t)b_k0 * N + bn + b_col;
    const float* Bp1 = Bp0 + (size_t)8 * N;  // only used when BN == 128

    unsigned long long acc[8][NP];
#pragma unroll
    for (int i = 0; i < 8; ++i)
#pragma unroll
        for (int j = 0; j < NP; ++j) acc[i][j] = 0ull;

    // prologue: fetch tile 0
    float4 pa0 = *(const float4*)(Ap0);
    float4 pa1 = *(const float4*)(Ap1);
    float4 pb0 = *(const float4*)(Bp0);
    float4 pb1;
    if (BN == 128) pb1 = *(const float4*)(Bp1);

    for (int k0 = 0; k0 < K; k0 += 16) {
        As[a_c0 + 0][a_row] = pa0.x;
        As[a_c0 + 1][a_row] = pa0.y;
        As[a_c0 + 2][a_row] = pa0.z;
        As[a_c0 + 3][a_row] = pa0.w;
        As[a_c0 + 8][a_row] = pa1.x;
        As[a_c0 + 9][a_row] = pa1.y;
        As[a_c0 + 10][a_row] = pa1.z;
        As[a_c0 + 11][a_row] = pa1.w;
        *(float4*)&Bs[b_k0][b_col] = pb0;
        if (BN == 128) *(float4*)&Bs[b_k0 + 8][b_col] = pb1;
        __syncthreads();

        if (k0 + 16 < K) {
            pa0 = *(const float4*)(Ap0 + k0 + 16);
            pa1 = *(const float4*)(Ap1 + k0 + 16);
            pb0 = *(const float4*)(Bp0 + (size_t)(k0 + 16) * N);
            if (BN == 128) pb1 = *(const float4*)(Bp1 + (size_t)(k0 + 16) * N);
        }

#pragma unroll
        for (int kk = 0; kk < 16; ++kk) {
            float af[8];
            *(float4*)&af[0] = *(const float4*)&As[kk][ty * 4];
            *(float4*)&af[4] = *(const float4*)&As[kk][ty * 4 + 64];
            unsigned long long bp[NP];
            {
                ulonglong2 t0 = *(const ulonglong2*)&Bs[kk][tx * 4];
                bp[0] = t0.x; bp[1] = t0.y;
                if (BN == 128) {
                    ulonglong2 t1 = *(const ulonglong2*)&Bs[kk][tx * 4 + 64];
                    bp[2] = t1.x; bp[3] = t1.y;
                }
            }
#pragma unroll
            for (int i = 0; i < 8; ++i) {
                unsigned long long aa = pack2(af[i], af[i]);
#pragma unroll
                for (int j = 0; j < NP; ++j)
                    acc[i][j] = fma2(aa, bp[j], acc[i][j]);
            }
        }
        __syncthreads();
    }

    // epilogue: acc[i][0..1] -> cols bn+tx*4..+3; acc[i][2..3] -> +64
#pragma unroll
    for (int ih = 0; ih < 2; ++ih) {
#pragma unroll
        for (int i = 0; i < 4; ++i) {
            const int row = bm + ih * 64 + ty * 4 + i;
            float* cp = C + (size_t)row * N + bn;
            ulonglong2 v0;
            v0.x = acc[ih * 4 + i][0];
            v0.y = acc[ih * 4 + i][1];
            *(ulonglong2*)(cp + tx * 4) = v0;
            if (BN == 128) {
                ulonglong2 v1;
                v1.x = acc[ih * 4 + i][2];
                v1.y = acc[ih * 4 + i][3];
                *(ulonglong2*)(cp + tx * 4 + 64) = v1;
            }
        }
    }
}

// ---------------------------------------------------------------------------
// BN stats, parallel: grid (C, nchunk); atomicAdd partial {sum, sumsq}.
// sums layout: sums[c] = sum, sums[256 + c] = sumsq.
// ---------------------------------------------------------------------------
__global__ void zero_sums_kernel(float* sums) {
    sums[blockIdx.x * 256 + threadIdx.x] = 0.0f;
}

__global__ void bn_stats_part_kernel(const float* __restrict__ Y,
                                     float* __restrict__ sums, int Ncols) {
    const int c = blockIdx.x;
    const int len = Ncols / gridDim.y;
    const float* row = Y + (size_t)c * Ncols + (size_t)blockIdx.y * len;
    float s = 0.0f, s2 = 0.0f;
    for (int i = threadIdx.x * 4; i < len; i += blockDim.x * 4) {
        float4 v = *(const float4*)(row + i);
        s += v.x + v.y + v.z + v.w;
        s2 += v.x * v.x + v.y * v.y + v.z * v.z + v.w * v.w;
    }
#pragma unroll
    for (int o = 16; o; o >>= 1) {
        s += __shfl_down_sync(0xFFFFFFFFu, s, o);
        s2 += __shfl_down_sync(0xFFFFFFFFu, s2, o);
    }
    __shared__ float ws[8], ws2[8];
    const int w = threadIdx.x >> 5, l = threadIdx.x & 31;
    if (l == 0) { ws[w] = s; ws2[w] = s2; }
    __syncthreads();
    if (threadIdx.x == 0) {
        float S = 0.0f, S2 = 0.0f;
        const int nw = blockDim.x >> 5;
        for (int i = 0; i < nw; ++i) { S += ws[i]; S2 += ws2[i]; }
        atomicAdd(&sums[c], S);
        atomicAdd(&sums[256 + c], S2);
    }
}

// ---------------------------------------------------------------------------
// BN apply + ReLU, in place on (C x Ncols); mean/rstd from raw sums
// ---------------------------------------------------------------------------
__global__ void bn_apply_ip_kernel(float* __restrict__ Y,
                                   const float* __restrict__ sums,
                                   const float* __restrict__ gamma,
                                   const float* __restrict__ beta,
                                   int Ncols, float invN) {
    size_t t = ((size_t)blockIdx.x * blockDim.x + threadIdx.x) * 4;
    const int c = (int)(t / Ncols);
    const float mean = sums[c] * invN;
    const float var = sums[256 + c] * invN - mean * mean;
    const float g = gamma[c] * rsqrtf(var + 1e-5f);
    const float b = beta[c] - mean * g;
    float4 v = *(float4*)(Y + t);
    v.x = fmaxf(v.x * g + b, 0.0f);
    v.y = fmaxf(v.y * g + b, 0.0f);
    v.z = fmaxf(v.z * g + b, 0.0f);
    v.w = fmaxf(v.w * g + b, 0.0f);
    *(float4*)(Y + t) = v;
}

// ---------------------------------------------------------------------------
// BN apply + ReLU, (C, B*N) -> out (B,C,N)
// ---------------------------------------------------------------------------
__global__ void bn_apply_out_kernel(const float* __restrict__ Y,
                                    const float* __restrict__ sums,
                                    const float* __restrict__ gamma,
                                    const float* __restrict__ beta,
                                    float* __restrict__ out,
                                    int B, int C, int N, float invN) {
    size_t t = ((size_t)blockIdx.x * blockDim.x + threadIdx.x) * 4;
    const int BN = B * N;
    const int c = (int)(t / BN);
    const int rem = (int)(t % BN);
    const int b = rem / N;
    const int n = rem % N;
    const float mean = sums[c] * invN;
    const float var = sums[256 + c] * invN - mean * mean;
    const float g = gamma[c] * rsqrtf(var + 1e-5f);
    const float bb = beta[c] - mean * g;
    float4 v = *(const float4*)(Y + t);
    v.x = fmaxf(v.x * g + bb, 0.0f);
    v.y = fmaxf(v.y * g + bb, 0.0f);
    v.z = fmaxf(v.z * g + bb, 0.0f);
    v.w = fmaxf(v.w * g + bb, 0.0f);
    *(float4*)(out + ((size_t)b * C + c) * N + n) = v;
}

// ---------------------------------------------------------------------------
// host driver
// ---------------------------------------------------------------------------
static inline void run_conv_bn_relu(const float* W, const float* X, float* Y,
                                    float* sums,
                                    const float* gamma, const float* beta,
                                    int M, int Ncols, int K, int bn_tile,
                                    bool apply_ip) {
    if (bn_tile == 64) {
        dim3 g(Ncols / 64, M / 128);
        sgemm_f32x2_kernel<64><<<g, 256>>>(W, X, Y, M, Ncols, K);
    } else {
        dim3 g(Ncols / 128, M / 128);
        sgemm_f32x2_kernel<128><<<g, 256>>>(W, X, Y, M, Ncols, K);
    }
    bn_stats_part_kernel<<<dim3(M, 8), 256>>>(Y, sums, Ncols);
    if (apply_ip) {
        int total = M * Ncols;
        bn_apply_ip_kernel<<<total / 1024, 256>>>(Y, sums, gamma, beta, Ncols,
                                                  1.0f / (float)Ncols);
    }
}

extern "C" void kernel_launch(void* const* d_in, const int* in_sizes, int n_in,
                              void* d_out, int out_size) {
    const float* in[26];
    for (int i = 0; i < 26 && i < n_in; ++i) in[i] = (const float*)d_in[i];

    const float *xyz0, *xyz1, *xyz2, *xyz3, *f0, *f1, *f2, *f3;
    if (in_sizes[1] == 8 * 64 * 8192) {  // interleaved: xyz0,f0,xyz1,f1,...
        xyz0 = in[0]; f0 = in[1]; xyz1 = in[2]; f1 = in[3];
        xyz2 = in[4]; f2 = in[5]; xyz3 = in[6]; f3 = in[7];
    } else {  // grouped
        xyz0 = in[0]; xyz1 = in[1]; xyz2 = in[2]; xyz3 = in[3];
        f0 = in[4]; f1 = in[5]; f2 = in[6]; f3 = in[7];
    }
    const float *w00 = in[8],  *g00 = in[9],  *b00 = in[10];
    const float *w01 = in[11], *g01 = in[12], *b01 = in[13];
    const float *w10 = in[14], *g10 = in[15], *b10 = in[16];
    const float *w11 = in[17], *g11 = in[18], *b11 = in[19];
    const float *w20 = in[20], *g20 = in[21], *b20 = in[22];
    const float *w21 = in[23], *g21 = in[24], *b21 = in[25];

    float *big, *Y00, *X2, *Y20, *F2N, *X1, *Y10, *F1N, *sums;
    cudaGetSymbolAddress((void**)&big, g_big);
    cudaGetSymbolAddress((void**)&Y00, g_Y00);
    cudaGetSymbolAddress((void**)&X2, g_X2);
    cudaGetSymbolAddress((void**)&Y20, g_Y20);
    cudaGetSymbolAddress((void**)&F2N, g_F2N);
    cudaGetSymbolAddress((void**)&X1, g_X1);
    cudaGetSymbolAddress((void**)&Y10, g_Y10);
    cudaGetSymbolAddress((void**)&F1N, g_F1N);
    cudaGetSymbolAddress((void**)&sums, g_sums);

    float* X0  = big;   // 192 x 65536 during FP0 concat + conv0
    float* Y01 = big;   // 128 x 65536 after conv0 (X0 dead: conv1 reads Y00)

    float* out = (float*)d_out;
    const int B = B_SZ;

    zero_sums_kernel<<<12, 256>>>(sums);

    // ---------------- FP2: xyz2 (n=512) <- xyz3 (m=128) ----------------
    {
        const int n = N2, m = N3, Cskip = 256, Cf = 512, cols = B * n;
        copy_skip_kernel<<<(B * Cskip * n) / 1024, 256>>>(f2, X2, B, Cskip, n);
        knn_interp_kernel<<<dim3(n / 256, B), 256>>>(
            xyz2, xyz3, f3, X2, n, m, Cf, Cskip, /*fb=*/Cf * m, /*fc=*/m, B);
        run_conv_bn_relu(w20, X2, Y20, sums + 0 * 512, g20, b20,
                         256, cols, 768, 64, true);
        run_conv_bn_relu(w21, Y20, F2N, sums + 1 * 512, g21, b21,
                         256, cols, 256, 64, true);
    }

    // ---------------- FP1: xyz1 (n=2048) <- xyz2 (m=512) ----------------
    {
        const int n = N1, m = N2, Cskip = 128, Cf = 256, cols = B * n;
        copy_skip_kernel<<<(B * Cskip * n) / 1024, 256>>>(f1, X1, B, Cskip, n);
        knn_interp_kernel<<<dim3(n / 256, B), 256>>>(
            xyz1, xyz2, F2N, X1, n, m, Cf, Cskip, /*fb=*/m, /*fc=*/B * m, B);
        run_conv_bn_relu(w10, X1, Y10, sums + 2 * 512, g10, b10,
                         256, cols, 384, 128, true);
        run_conv_bn_relu(w11, Y10, F1N, sums + 3 * 512, g11, b11,
                         128, cols, 256, 128, true);
    }

    // ---------------- FP0: xyz0 (n=8192) <- xyz1 (m=2048) ----------------
    {
        const int n = N0, m = N1, Cskip = 64, Cf = 128, cols = B * n;
        copy_skip_kernel<<<(B * Cskip * n) / 1024, 256>>>(f0, X0, B, Cskip, n);
        knn_interp_kernel<<<dim3(n / 256, B), 256>>>(
            xyz0, xyz1, F1N, X0, n, m, Cf, Cskip, /*fb=*/m, /*fc=*/B * m, B);
        run_conv_bn_relu(w00, X0, Y00, sums + 4 * 512, g00, b00,
                         128, cols, 192, 128, true);
        run_conv_bn_relu(w01, Y00, Y01, sums + 5 * 512, g01, b01,
                         128, cols, 128, 128, false);
        const int total = 128 * cols;
        bn_apply_out_kernel<<<total / 1024, 256>>>(Y01, sums + 5 * 512, g01,
                                                   b01, out, B, 128, n,
                                                   1.0f / (float)cols);
    }
}

// round 14
// speedup vs baseline: 1.0683x; 1.0023x over previous
#include <cuda_runtime.h>
#include <cstdint>

// ---------------------------------------------------------------------------
// PointNet++ decoder. Conv1x1 GEMMs on the fp32 pipe using Blackwell packed
// fma.rn.f32x2 (FFMA2: 2 FMA per issue slot -> 2x the FFMA-3reg ceiling).
// Layout: X is (C_rows, B*N cols) row-major; convs are single GEMMs; BN stats
// are row reductions (split 8-way + atomics).
// Target is sm_100 (no 'a'): no tcgen05, no kind::tf32.
// ---------------------------------------------------------------------------

#define B_SZ 8
#define N0 8192
#define N1 2048
#define N2 512
#define N3 128

__device__ float g_big[192 * (B_SZ * N0)];   // X0; later aliased as Y01
__device__ float g_Y00[128 * (B_SZ * N0)];
__device__ float g_X2[768 * (B_SZ * N2)];
__device__ float g_Y20[256 * (B_SZ * N2)];
__device__ float g_F2N[256 * (B_SZ * N2)];
__device__ float g_X1[384 * (B_SZ * N1)];
__device__ float g_Y10[256 * (B_SZ * N1)];
__device__ float g_F1N[128 * (B_SZ * N1)];
__device__ float g_sums[6 * 512];  // per layer: [0,256)=sum, [256,512)=sumsq

// ---------------- packed f32x2 helpers ----------------
__device__ __forceinline__ unsigned long long pack2(float x, float y) {
    unsigned long long r;
    asm("mov.b64 %0, {%1, %2};" : "=l"(r) : "f"(x), "f"(y));
    return r;
}
__device__ __forceinline__ unsigned long long fma2(unsigned long long a,
                                                   unsigned long long b,
                                                   unsigned long long c) {
    unsigned long long d;
    asm("fma.rn.f32x2 %0, %1, %2, %3;" : "=l"(d) : "l"(a), "l"(b), "l"(c));
    return d;
}

// ---------------------------------------------------------------------------
// copy skip features (B,C,N) -> X rows [0,C), layout (C, B*N)
// ---------------------------------------------------------------------------
__global__ void copy_skip_kernel(const float* __restrict__ src,
                                 float* __restrict__ dst,
                                 int B, int C, int N) {
    size_t t = ((size_t)blockIdx.x * blockDim.x + threadIdx.x) * 4;
    int BN = B * N;
    int c = (int)(t / BN);
    int rem = (int)(t % BN);
    int b = rem / N;
    int n = rem % N;
    *(float4*)(dst + t) =
        *(const float4*)(src + ((size_t)b * C + c) * N + n);
}

// ---------------------------------------------------------------------------
// kNN(3) + inverse-distance interpolation (channel-major feats).
// ---------------------------------------------------------------------------
__global__ void knn_interp_kernel(const float* __restrict__ uxyz,
                                  const float* __restrict__ kxyz,
                                  const float* __restrict__ feats,
                                  float* __restrict__ X,
                                  int n, int m, int C, int c0,
                                  int fb, int fc, int B) {
    __shared__ float skx[2048];
    __shared__ float sky[2048];
    __shared__ float skz[2048];

    const int b = blockIdx.y;
    const int pi = blockIdx.x * blockDim.x + threadIdx.x;

    for (int j = threadIdx.x; j < m; j += blockDim.x) {
        const float* p = kxyz + ((size_t)b * m + j) * 3;
        skx[j] = p[0];
        sky[j] = p[1];
        skz[j] = p[2];
    }
    __syncthreads();
    if (pi >= n) return;

    const float* up = uxyz + ((size_t)b * n + pi) * 3;
    const float ux = up[0], uy = up[1], uz = up[2];

    float d0 = 1e30f, d1 = 1e30f, d2 = 1e30f;
    int i0 = 0, i1 = 0, i2 = 0;
    for (int j = 0; j < m; ++j) {
        float dx = ux - skx[j];
        float dy = uy - sky[j];
        float dz = uz - skz[j];
        float d = dx * dx + dy * dy + dz * dz;
        if (d < d2) {
            if (d < d1) {
                d2 = d1; i2 = i1;
                if (d < d0) { d1 = d0; i1 = i0; d0 = d; i0 = j; }
                else        { d1 = d;  i1 = j; }
            } else {
                d2 = d; i2 = j;
            }
        }
    }

    float r0 = 1.0f / (d0 + 1e-8f);
    float r1 = 1.0f / (d1 + 1e-8f);
    float r2 = 1.0f / (d2 + 1e-8f);
    float rs = 1.0f / (r0 + r1 + r2);
    const float w0 = r0 * rs, w1 = r1 * rs, w2 = r2 * rs;

    const float* fbase = feats + (size_t)b * fb;
    const size_t ocol = (size_t)b * n + pi;
    const size_t rowstride = (size_t)B * n;
    float* outp = X + (size_t)c0 * rowstride + ocol;
    for (int c = 0; c < C; ++c) {
        const float* fr = fbase + (size_t)c * fc;
        outp[(size_t)c * rowstride] = w0 * fr[i0] + w1 * fr[i1] + w2 * fr[i2];
    }
}

// ---------------------------------------------------------------------------
// SGEMM with packed f32x2 FMA: C(M x N) = A(M x K) @ B(K x N), row-major.
// CTA tile 128 x BN x 16 (BN = 128 or 64), 256 threads, micro-tile 8 x (BN/16),
// accumulators are f32x2 pairs along N. Register-prefetch double buffering.
// M in {128,256}, N % BN == 0, K % 16 == 0 (exact for this problem).
// ---------------------------------------------------------------------------
template <int BN>
__global__ __launch_bounds__(256) void sgemm_f32x2_kernel(
    const float* __restrict__ A, const float* __restrict__ B,
    float* __restrict__ C, int M, int N, int K) {
    constexpr int NP = BN / 32;  // f32x2 pairs per thread along N (4 or 2)
    __shared__ float As[16][128];  // As[k][m]
    __shared__ float Bs[16][BN];   // Bs[k][n]

    const int tid = threadIdx.x;
    const int bm = blockIdx.y * 128;
    const int bn = blockIdx.x * BN;
    const int tx = tid & 15;    // col group: covers tx*4 (+64 when BN=128)
    const int ty = tid >> 4;    // row group: covers ty*4 + {0..3}, +64

    // A loaders: 512 float4/tile; thread t -> {t, t+256}
    const int a_row = tid & 127;
    const int a_c0 = (tid >> 7) * 4;  // 0 or 4
    const float* Ap0 = A + (size_t)(bm + a_row) * K + a_c0;
    const float* Ap1 = Ap0 + 8;

    // B loaders
    int b_k0, b_col;
    if (BN == 128) { b_k0 = tid >> 5; b_col = (tid & 31) * 4; }  // 2 ld/thread
    else           { b_k0 = tid >> 4; b_col = (tid & 15) * 4; }  // 1 ld/thread
    const float* Bp0 = B + (size_t)b_k0 * N + bn + b_col;
    const float* Bp1 = Bp0 + (size_t)8 * N;  // only used when BN == 128

    unsigned long long acc[8][NP];
#pragma unroll
    for (int i = 0; i < 8; ++i)
#pragma unroll
        for (int j = 0; j < NP; ++j) acc[i][j] = 0ull;

    // prologue: fetch tile 0
    float4 pa0 = *(const float4*)(Ap0);
    float4 pa1 = *(const float4*)(Ap1);
    float4 pb0 = *(const float4*)(Bp0);
    float4 pb1;
    if (BN == 128) pb1 = *(const float4*)(Bp1);

    for (int k0 = 0; k0 < K; k0 += 16) {
        As[a_c0 + 0][a_row] = pa0.x;
        As[a_c0 + 1][a_row] = pa0.y;
        As[a_c0 + 2][a_row] = pa0.z;
        As[a_c0 + 3][a_row] = pa0.w;
        As[a_c0 + 8][a_row] = pa1.x;
        As[a_c0 + 9][a_row] = pa1.y;
        As[a_c0 + 10][a_row] = pa1.z;
        As[a_c0 + 11][a_row] = pa1.w;
        *(float4*)&Bs[b_k0][b_col] = pb0;
        if (BN == 128) *(float4*)&Bs[b_k0 + 8][b_col] = pb1;
        __syncthreads();

        if (k0 + 16 < K) {
            pa0 = *(const float4*)(Ap0 + k0 + 16);
            pa1 = *(const float4*)(Ap1 + k0 + 16);
            pb0 = *(const float4*)(Bp0 + (size_t)(k0 + 16) * N);
            if (BN == 128) pb1 = *(const float4*)(Bp1 + (size_t)(k0 + 16) * N);
        }

#pragma unroll
        for (int kk = 0; kk < 16; ++kk) {
            float af[8];
            *(float4*)&af[0] = *(const float4*)&As[kk][ty * 4];
            *(float4*)&af[4] = *(const float4*)&As[kk][ty * 4 + 64];
            unsigned long long bp[NP];
            {
                ulonglong2 t0 = *(const ulonglong2*)&Bs[kk][tx * 4];
                bp[0] = t0.x; bp[1] = t0.y;
                if (BN == 128) {
                    ulonglong2 t1 = *(const ulonglong2*)&Bs[kk][tx * 4 + 64];
                    bp[2] = t1.x; bp[3] = t1.y;
                }
            }
#pragma unroll
            for (int i = 0; i < 8; ++i) {
                unsigned long long aa = pack2(af[i], af[i]);
#pragma unroll
                for (int j = 0; j < NP; ++j)
                    acc[i][j] = fma2(aa, bp[j], acc[i][j]);
            }
        }
        __syncthreads();
    }

    // epilogue: acc[i][0..1] -> cols bn+tx*4..+3; acc[i][2..3] -> +64
#pragma unroll
    for (int ih = 0; ih < 2; ++ih) {
#pragma unroll
        for (int i = 0; i < 4; ++i) {
            const int row = bm + ih * 64 + ty * 4 + i;
            float* cp = C + (size_t)row * N + bn;
            ulonglong2 v0;
            v0.x = acc[ih * 4 + i][0];
            v0.y = acc[ih * 4 + i][1];
            *(ulonglong2*)(cp + tx * 4) = v0;
            if (BN == 128) {
                ulonglong2 v1;
                v1.x = acc[ih * 4 + i][2];
                v1.y = acc[ih * 4 + i][3];
                *(ulonglong2*)(cp + tx * 4 + 64) = v1;
            }
        }
    }
}

// ---------------------------------------------------------------------------
// BN stats, parallel: grid (C, nchunk); atomicAdd partial {sum, sumsq}.
// sums layout: sums[c] = sum, sums[256 + c] = sumsq.
// ---------------------------------------------------------------------------
__global__ void zero_sums_kernel(float* sums) {
    sums[blockIdx.x * 256 + threadIdx.x] = 0.0f;
}

__global__ void bn_stats_part_kernel(const float* __restrict__ Y,
                                     float* __restrict__ sums, int Ncols) {
    const int c = blockIdx.x;
    const int len = Ncols / gridDim.y;
    const float* row = Y + (size_t)c * Ncols + (size_t)blockIdx.y * len;
    float s = 0.0f, s2 = 0.0f;
    for (int i = threadIdx.x * 4; i < len; i += blockDim.x * 4) {
        float4 v = *(const float4*)(row + i);
        s += v.x + v.y + v.z + v.w;
        s2 += v.x * v.x + v.y * v.y + v.z * v.z + v.w * v.w;
    }
#pragma unroll
    for (int o = 16; o; o >>= 1) {
        s += __shfl_down_sync(0xFFFFFFFFu, s, o);
        s2 += __shfl_down_sync(0xFFFFFFFFu, s2, o);
    }
    __shared__ float ws[8], ws2[8];
    const int w = threadIdx.x >> 5, l = threadIdx.x & 31;
    if (l == 0) { ws[w] = s; ws2[w] = s2; }
    __syncthreads();
    if (threadIdx.x == 0) {
        float S = 0.0f, S2 = 0.0f;
        const int nw = blockDim.x >> 5;
        for (int i = 0; i < nw; ++i) { S += ws[i]; S2 += ws2[i]; }
        atomicAdd(&sums[c], S);
        atomicAdd(&sums[256 + c], S2);
    }
}

// ---------------------------------------------------------------------------
// BN apply + ReLU, in place on (C x Ncols); mean/rstd from raw sums
// ---------------------------------------------------------------------------
__global__ void bn_apply_ip_kernel(float* __restrict__ Y,
                                   const float* __restrict__ sums,
                                   const float* __restrict__ gamma,
                                   const float* __restrict__ beta,
                                   int Ncols, float invN) {
    size_t t = ((size_t)blockIdx.x * blockDim.x + threadIdx.x) * 4;
    const int c = (int)(t / Ncols);
    const float mean = sums[c] * invN;
    const float var = sums[256 + c] * invN - mean * mean;
    const float g = gamma[c] * rsqrtf(var + 1e-5f);
    const float b = beta[c] - mean * g;
    float4 v = *(float4*)(Y + t);
    v.x = fmaxf(v.x * g + b, 0.0f);
    v.y = fmaxf(v.y * g + b, 0.0f);
    v.z = fmaxf(v.z * g + b, 0.0f);
    v.w = fmaxf(v.w * g + b, 0.0f);
    *(float4*)(Y + t) = v;
}

// ---------------------------------------------------------------------------
// BN apply + ReLU, (C, B*N) -> out (B,C,N)
// ---------------------------------------------------------------------------
__global__ void bn_apply_out_kernel(const float* __restrict__ Y,
                                    const float* __restrict__ sums,
                                    const float* __restrict__ gamma,
                                    const float* __restrict__ beta,
                                    float* __restrict__ out,
                                    int B, int C, int N, float invN) {
    size_t t = ((size_t)blockIdx.x * blockDim.x + threadIdx.x) * 4;
    const int BN = B * N;
    const int c = (int)(t / BN);
    const int rem = (int)(t % BN);
    const int b = rem / N;
    const int n = rem % N;
    const float mean = sums[c] * invN;
    const float var = sums[256 + c] * invN - mean * mean;
    const float g = gamma[c] * rsqrtf(var + 1e-5f);
    const float bb = beta[c] - mean * g;
    float4 v = *(const float4*)(Y + t);
    v.x = fmaxf(v.x * g + bb, 0.0f);
    v.y = fmaxf(v.y * g + bb, 0.0f);
    v.z = fmaxf(v.z * g + bb, 0.0f);
    v.w = fmaxf(v.w * g + bb, 0.0f);
    *(float4*)(out + ((size_t)b * C + c) * N + n) = v;
}

// ---------------------------------------------------------------------------
// host driver
// ---------------------------------------------------------------------------
static inline void run_conv_bn_relu(const float* W, const float* X, float* Y,
                                    float* sums,
                                    const float* gamma, const float* beta,
                                    int M, int Ncols, int K, int bn_tile,
                                    bool apply_ip) {
    if (bn_tile == 64) {
        dim3 g(Ncols / 64, M / 128);
        sgemm_f32x2_kernel<64><<<g, 256>>>(W, X, Y, M, Ncols, K);
    } else {
        dim3 g(Ncols / 128, M / 128);
        sgemm_f32x2_kernel<128><<<g, 256>>>(W, X, Y, M, Ncols, K);
    }
    bn_stats_part_kernel<<<dim3(M, 8), 256>>>(Y, sums, Ncols);
    if (apply_ip) {
        int total = M * Ncols;
        bn_apply_ip_kernel<<<total / 1024, 256>>>(Y, sums, gamma, beta, Ncols,
                                                  1.0f / (float)Ncols);
    }
}

extern "C" void kernel_launch(void* const* d_in, const int* in_sizes, int n_in,
                              void* d_out, int out_size) {
    const float* in[26];
    for (int i = 0; i < 26 && i < n_in; ++i) in[i] = (const float*)d_in[i];

    const float *xyz0, *xyz1, *xyz2, *xyz3, *f0, *f1, *f2, *f3;
    if (in_sizes[1] == 8 * 64 * 8192) {  // interleaved: xyz0,f0,xyz1,f1,...
        xyz0 = in[0]; f0 = in[1]; xyz1 = in[2]; f1 = in[3];
        xyz2 = in[4]; f2 = in[5]; xyz3 = in[6]; f3 = in[7];
    } else {  // grouped
        xyz0 = in[0]; xyz1 = in[1]; xyz2 = in[2]; xyz3 = in[3];
        f0 = in[4]; f1 = in[5]; f2 = in[6]; f3 = in[7];
    }
    const float *w00 = in[8],  *g00 = in[9],  *b00 = in[10];
    const float *w01 = in[11], *g01 = in[12], *b01 = in[13];
    const float *w10 = in[14], *g10 = in[15], *b10 = in[16];
    const float *w11 = in[17], *g11 = in[18], *b11 = in[19];
    const float *w20 = in[20], *g20 = in[21], *b20 = in[22];
    const float *w21 = in[23], *g21 = in[24], *b21 = in[25];

    float *big, *Y00, *X2, *Y20, *F2N, *X1, *Y10, *F1N, *sums;
    cudaGetSymbolAddress((void**)&big, g_big);
    cudaGetSymbolAddress((void**)&Y00, g_Y00);
    cudaGetSymbolAddress((void**)&X2, g_X2);
    cudaGetSymbolAddress((void**)&Y20, g_Y20);
    cudaGetSymbolAddress((void**)&F2N, g_F2N);
    cudaGetSymbolAddress((void**)&X1, g_X1);
    cudaGetSymbolAddress((void**)&Y10, g_Y10);
    cudaGetSymbolAddress((void**)&F1N, g_F1N);
    cudaGetSymbolAddress((void**)&sums, g_sums);

    float* X0  = big;   // 192 x 65536 during FP0 concat + conv0
    float* Y01 = big;   // 128 x 65536 after conv0 (X0 dead: conv1 reads Y00)

    float* out = (float*)d_out;
    const int B = B_SZ;

    zero_sums_kernel<<<12, 256>>>(sums);

    // ---------------- FP2: xyz2 (n=512) <- xyz3 (m=128) ----------------
    {
        const int n = N2, m = N3, Cskip = 256, Cf = 512, cols = B * n;
        copy_skip_kernel<<<(B * Cskip * n) / 1024, 256>>>(f2, X2, B, Cskip, n);
        knn_interp_kernel<<<dim3(n / 256, B), 256>>>(
            xyz2, xyz3, f3, X2, n, m, Cf, Cskip, /*fb=*/Cf * m, /*fc=*/m, B);
        run_conv_bn_relu(w20, X2, Y20, sums + 0 * 512, g20, b20,
                         256, cols, 768, 64, true);
        run_conv_bn_relu(w21, Y20, F2N, sums + 1 * 512, g21, b21,
                         256, cols, 256, 64, true);
    }

    // ---------------- FP1: xyz1 (n=2048) <- xyz2 (m=512) ----------------
    {
        const int n = N1, m = N2, Cskip = 128, Cf = 256, cols = B * n;
        copy_skip_kernel<<<(B * Cskip * n) / 1024, 256>>>(f1, X1, B, Cskip, n);
        knn_interp_kernel<<<dim3(n / 256, B), 256>>>(
            xyz1, xyz2, F2N, X1, n, m, Cf, Cskip, /*fb=*/m, /*fc=*/B * m, B);
        run_conv_bn_relu(w10, X1, Y10, sums + 2 * 512, g10, b10,
                         256, cols, 384, 128, true);
        run_conv_bn_relu(w11, Y10, F1N, sums + 3 * 512, g11, b11,
                         128, cols, 256, 128, true);
    }

    // ---------------- FP0: xyz0 (n=8192) <- xyz1 (m=2048) ----------------
    {
        const int n = N0, m = N1, Cskip = 64, Cf = 128, cols = B * n;
        copy_skip_kernel<<<(B * Cskip * n) / 1024, 256>>>(f0, X0, B, Cskip, n);
        knn_interp_kernel<<<dim3(n / 256, B), 256>>>(
            xyz0, xyz1, F1N, X0, n, m, Cf, Cskip, /*fb=*/m, /*fc=*/B * m, B);
        run_conv_bn_relu(w00, X0, Y00, sums + 4 * 512, g00, b00,
                         128, cols, 192, 128, true);
        run_conv_bn_relu(w01, Y00, Y01, sums + 5 * 512, g01, b01,
                         128, cols, 128, 128, false);
        const int total = 128 * cols;
        bn_apply_out_kernel<<<total / 1024, 256>>>(Y01, sums + 5 * 512, g01,
                                                   b01, out, B, 128, n,
                                                   1.0f / (float)cols);
    }
}